// round 2
// baseline (speedup 1.0000x reference)
#include <cuda_runtime.h>
#include <cuda_bf16.h>

#define BB 512
#define LL 512
#define NN 128
#define NB 2    // batches per forward block

// Scratch (device globals — no allocation allowed)
__device__ unsigned long long g_E2[64 * NN];  // packed pairs (E[2i][j], E[2i+1][j])
__device__ float g_norm[BB];
__device__ float g_path[BB];

__device__ __forceinline__ unsigned long long ffma2(unsigned long long a,
                                                    unsigned long long b,
                                                    unsigned long long c) {
    unsigned long long d;
    asm("fma.rn.f32x2 %0, %1, %2, %3;" : "=l"(d) : "l"(a), "l"(b), "l"(c));
    return d;
}
__device__ __forceinline__ unsigned long long pack2(float a, float b) {
    unsigned long long r;
    asm("mov.b64 %0, {%1,%2};" : "=l"(r) : "f"(a), "f"(b));
    return r;
}
__device__ __forceinline__ float lo32(unsigned long long v) {
    return __uint_as_float((unsigned int)v);
}
__device__ __forceinline__ float hi32(unsigned long long v) {
    return __uint_as_float((unsigned int)(v >> 32));
}

// ---------------------------------------------------------------------------
// Kernel 0: packed E = exp(trans), pair layout for f32x2 FMA
// g_E2[ii*128 + j] = pack( exp(trans[2ii][j]), exp(trans[2ii+1][j]) )
// ---------------------------------------------------------------------------
__global__ void crf_expE(const float* __restrict__ trans) {
    int idx = blockIdx.x * blockDim.x + threadIdx.x;   // 0 .. 64*128-1
    int ii = idx >> 7, j = idx & 127;
    float e0 = __expf(trans[(2 * ii) * NN + j]);
    float e1 = __expf(trans[(2 * ii + 1) * NN + j]);
    g_E2[idx] = pack2(e0, e1);
}

// ---------------------------------------------------------------------------
// Kernel 1: forward recurrence. 256 blocks x 128 threads, 2 batches/block.
// Thread j owns state j for both batches; full E column in registers.
// One __syncthreads per step; p double-buffered by parity; shift constant c
// is the previous step's state-0 score (no max needed).
// ---------------------------------------------------------------------------
__global__ __launch_bounds__(128, 2)
void crf_forward(const float* __restrict__ em,
                 const float* __restrict__ mask,
                 const float* __restrict__ start) {
    __shared__ ulonglong2 pfu[2][NB][32];   // p vectors (float[128] aliased)
    __shared__ float      csh[2][NB];       // shift constants, parity buffered
    __shared__ float      red[NB][NN];      // final reduction

    const int j  = threadIdx.x;
    const int b0 = blockIdx.x * NB;

    // E column in registers: 64 packed pairs
    unsigned long long E2[64];
#pragma unroll
    for (int ii = 0; ii < 64; ii++) E2[ii] = g_E2[ii * NN + j];

    const float* em0 = em + (size_t)b0 * LL * NN;
    const float* em1 = em + (size_t)(b0 + 1) * LL * NN;
    const float* mk0p = mask + (size_t)b0 * LL;
    const float* mk1p = mask + (size_t)(b0 + 1) * LL;

    float s0 = start[j] + em0[j];
    float s1 = start[j] + em1[j];
    if (j == 0) { csh[0][0] = s0; csh[0][1] = s1; }
    __syncthreads();
    float cp0 = csh[0][0], cp1 = csh[0][1];
    ((float*)&pfu[1][0][0])[j] = __expf(s0 - cp0);
    ((float*)&pfu[1][1][0])[j] = __expf(s1 - cp1);
    float em_r0 = em0[NN + j];
    float em_r1 = em1[NN + j];
    float mk0 = mk0p[1];
    float mk1 = mk1p[1];
    __syncthreads();

    for (int t = 1; t < LL; t++) {
        const int par = t & 1;

        // ---- B: full dot products, f32x2 FMA, E in registers ----
        unsigned long long a0 = 0ull, a1 = 0ull;
        const ulonglong2* p0 = pfu[par][0];
        const ulonglong2* p1 = pfu[par][1];
#pragma unroll 8
        for (int w = 0; w < 32; w++) {
            ulonglong2 v0 = p0[w];                 // broadcast LDS.128
            a0 = ffma2(v0.x, E2[2 * w], a0);
            a0 = ffma2(v0.y, E2[2 * w + 1], a0);
            ulonglong2 v1 = p1[w];
            a1 = ffma2(v1.x, E2[2 * w], a1);
            a1 = ffma2(v1.y, E2[2 * w + 1], a1);
        }
        float tot0 = lo32(a0) + hi32(a0);
        float tot1 = lo32(a1) + hi32(a1);

        // ---- C: log + emission + mask blend, build next p ----
        float n0 = cp0 + __logf(tot0) + em_r0;
        float n1 = cp1 + __logf(tot1) + em_r1;
        s0 = mk0 * n0 + (1.0f - mk0) * s0;
        s1 = mk1 * n1 + (1.0f - mk1) * s1;
        if (j == 0) { csh[par][0] = s0; csh[par][1] = s1; }
        float cn0 = csh[par ^ 1][0];   // = s_{t-1}(g,0), written last iter
        float cn1 = csh[par ^ 1][1];
        ((float*)&pfu[par ^ 1][0][0])[j] = __expf(s0 - cn0);
        ((float*)&pfu[par ^ 1][1][0])[j] = __expf(s1 - cn1);
        cp0 = cn0; cp1 = cn1;

        // ---- prefetch next emission / mask ----
        if (t + 1 < LL) {
            em_r0 = em0[(size_t)(t + 1) * NN + j];
            em_r1 = em1[(size_t)(t + 1) * NN + j];
            mk0 = mk0p[t + 1];
            mk1 = mk1p[t + 1];
        }
        __syncthreads();
    }

    // ---- final logsumexp over states, per batch ----
    red[0][j] = s0;
    red[1][j] = s1;
    __syncthreads();
    const int w = j >> 5, lane = j & 31;
    if (w < NB) {
        float a = red[w][lane];
        float b = red[w][lane + 32];
        float c = red[w][lane + 64];
        float d = red[w][lane + 96];
        float mx = fmaxf(fmaxf(a, b), fmaxf(c, d));
#pragma unroll
        for (int o = 16; o; o >>= 1)
            mx = fmaxf(mx, __shfl_xor_sync(0xffffffffu, mx, o));
        float sum = __expf(a - mx) + __expf(b - mx) +
                    __expf(c - mx) + __expf(d - mx);
#pragma unroll
        for (int o = 16; o; o >>= 1)
            sum += __shfl_xor_sync(0xffffffffu, sum, o);
        if (lane == 0) g_norm[b0 + w] = mx + __logf(sum);
    }
}

// ---------------------------------------------------------------------------
// Kernel 2: path score. One block (128 threads) per batch.
// ---------------------------------------------------------------------------
__global__ __launch_bounds__(128)
void crf_path(const float* __restrict__ em,
              const int*   __restrict__ tgt,
              const float* __restrict__ mask,
              const float* __restrict__ start,
              const float* __restrict__ trans) {
    const int b = blockIdx.x;
    const int tid = threadIdx.x;
    __shared__ float red[128];

    const size_t embase = (size_t)b * LL * NN;
    float s = 0.0f;
    for (int t = tid; t < LL; t += 128) {
        if (t == 0) {
            int t0 = tgt[b * LL];
            s += start[t0] + em[embase + t0];
        } else {
            int prev = tgt[b * LL + t - 1];
            int cur  = tgt[b * LL + t];
            s += mask[b * LL + t] *
                 (trans[prev * NN + cur] + em[embase + (size_t)t * NN + cur]);
        }
    }
    red[tid] = s;
    __syncthreads();
#pragma unroll
    for (int o = 64; o; o >>= 1) {
        if (tid < o) red[tid] += red[tid + o];
        __syncthreads();
    }
    if (tid == 0) g_path[b] = red[0];
}

// ---------------------------------------------------------------------------
// Kernel 3: mean(normalizer - path), shuffle-based
// ---------------------------------------------------------------------------
__global__ __launch_bounds__(512)
void crf_final(float* __restrict__ out) {
    const int tid = threadIdx.x;
    __shared__ float wsum[16];
    float v = g_norm[tid] - g_path[tid];
#pragma unroll
    for (int o = 16; o; o >>= 1) v += __shfl_xor_sync(0xffffffffu, v, o);
    if ((tid & 31) == 0) wsum[tid >> 5] = v;
    __syncthreads();
    if (tid < 32) {
        float x = (tid < 16) ? wsum[tid] : 0.0f;
#pragma unroll
        for (int o = 8; o; o >>= 1) x += __shfl_xor_sync(0xffffffffu, x, o);
        if (tid == 0) out[0] = x * (1.0f / (float)BB);
    }
}

// ---------------------------------------------------------------------------
// Launch
// ---------------------------------------------------------------------------
extern "C" void kernel_launch(void* const* d_in, const int* in_sizes, int n_in,
                              void* d_out, int out_size) {
    const float* emission    = (const float*)d_in[0];
    const int*   target      = (const int*)  d_in[1];
    const float* mask        = (const float*)d_in[2];
    const float* start_trans = (const float*)d_in[3];
    const float* trans       = (const float*)d_in[4];
    float* out = (float*)d_out;

    crf_expE<<<64, 128>>>(trans);
    crf_forward<<<BB / NB, 128>>>(emission, mask, start_trans);
    crf_path<<<BB, 128>>>(emission, target, mask, start_trans, trans);
    crf_final<<<1, 512>>>(out);
}

// round 3
// speedup vs baseline: 1.7929x; 1.7929x over previous
#include <cuda_runtime.h>
#include <cuda_bf16.h>

#define BB 512
#define LL 512
#define NN 128
#define GG 2    // batches per forward block

// Scratch (device globals — no allocation allowed)
__device__ unsigned long long g_E2[64 * NN];  // {E[2r][c], E[2r+1][c]} at [r*128+c]
__device__ float g_norm[BB];
__device__ float g_path[BB];

__device__ __forceinline__ unsigned long long ffma2(unsigned long long a,
                                                    unsigned long long b,
                                                    unsigned long long c) {
    unsigned long long d;
    asm("fma.rn.f32x2 %0, %1, %2, %3;" : "=l"(d) : "l"(a), "l"(b), "l"(c));
    return d;
}
__device__ __forceinline__ unsigned long long pack2(float a, float b) {
    unsigned long long r;
    asm("mov.b64 %0, {%1,%2};" : "=l"(r) : "f"(a), "f"(b));
    return r;
}
__device__ __forceinline__ float lo32(unsigned long long v) {
    return __uint_as_float((unsigned int)v);
}
__device__ __forceinline__ float hi32(unsigned long long v) {
    return __uint_as_float((unsigned int)(v >> 32));
}

// ---------------------------------------------------------------------------
// Kernel 0: packed E = exp(trans): g_E2[r*128+c] = {exp(T[2r][c]), exp(T[2r+1][c])}
// ---------------------------------------------------------------------------
__global__ void crf_expE(const float* __restrict__ trans) {
    int idx = blockIdx.x * blockDim.x + threadIdx.x;   // 0 .. 64*128-1
    int r = idx >> 7, c = idx & 127;
    float e0 = __expf(trans[(2 * r) * NN + c]);
    float e1 = __expf(trans[(2 * r + 1) * NN + c]);
    g_E2[idx] = pack2(e0, e1);
}

// ---------------------------------------------------------------------------
// Kernel 1: forward recurrence. 256 blocks x 256 threads, 2 batches/block,
// 2 blocks/SM. Phase B role: thread (q = tid>>6, jj = tid&63) computes
// partials for output cols {jj, jj+64}, i-slice [32q,32q+32), both batches.
// Phase C role: thread (g = tid>>7, j = tid&127) owns score s[g][j].
// Shift constant = one-step-stale state-0 score (no max phase).
// Two __syncthreads per step.
// ---------------------------------------------------------------------------
__global__ __launch_bounds__(256, 2)
void crf_forward(const float* __restrict__ em,
                 const float* __restrict__ mask,
                 const float* __restrict__ start) {
    __shared__ __align__(16) float psh[GG][NN];   // p vectors
    __shared__ float part[4][GG][NN];             // i-slice partials
    __shared__ float csh[2][GG];                  // parity-buffered shifts
    __shared__ float sred[GG][NN];                // final reduction

    const int tid = threadIdx.x;
    const int q  = tid >> 6;      // 0..3  (phase B i-slice)
    const int jj = tid & 63;      // phase B column base
    const int g  = tid >> 7;      // 0..1  (phase C batch)
    const int j  = tid & 127;     // phase C state
    const int b0 = blockIdx.x * GG;

    // E in registers: pairs for cols jj and jj+64, rows [32q, 32q+32)
    unsigned long long Ea[16], Eb[16];
#pragma unroll
    for (int m = 0; m < 16; m++) {
        Ea[m] = g_E2[(16 * q + m) * NN + jj];
        Eb[m] = g_E2[(16 * q + m) * NN + 64 + jj];
    }

    const float* emg = em + (size_t)(b0 + g) * LL * NN;
    const float* mkg = mask + (size_t)(b0 + g) * LL;

    // ---- init: s0 = start + em[.,0,.] ; p0 = exp(s0 - s0[0]) ----
    float s = start[j] + emg[j];
    if (j == 0) csh[0][g] = s;
    __syncthreads();
    float cp = csh[0][g];
    psh[g][j] = __expf(s - cp);
    float em_r = emg[NN + j];
    float mk_r = mkg[1];
    __syncthreads();

    for (int t = 1; t < LL; t++) {
        // -------- Phase B: partial dots, 1 LDS.128 : 4 FFMA2 --------
        unsigned long long a00 = 0ull, a10 = 0ull;   // cols {jj, jj+64}, batch 0
        unsigned long long a01 = 0ull, a11 = 0ull;   // cols {jj, jj+64}, batch 1
        const ulonglong2* p0 = ((const ulonglong2*)&psh[0][0]) + q * 8;
        const ulonglong2* p1 = ((const ulonglong2*)&psh[1][0]) + q * 8;
#pragma unroll
        for (int k = 0; k < 8; k++) {
            ulonglong2 v0 = p0[k];                    // broadcast
            a00 = ffma2(v0.x, Ea[2 * k], a00);
            a00 = ffma2(v0.y, Ea[2 * k + 1], a00);
            a10 = ffma2(v0.x, Eb[2 * k], a10);
            a10 = ffma2(v0.y, Eb[2 * k + 1], a10);
            ulonglong2 v1 = p1[k];
            a01 = ffma2(v1.x, Ea[2 * k], a01);
            a01 = ffma2(v1.y, Ea[2 * k + 1], a01);
            a11 = ffma2(v1.x, Eb[2 * k], a11);
            a11 = ffma2(v1.y, Eb[2 * k + 1], a11);
        }
        part[q][0][jj]      = lo32(a00) + hi32(a00);
        part[q][0][jj + 64] = lo32(a10) + hi32(a10);
        part[q][1][jj]      = lo32(a01) + hi32(a01);
        part[q][1][jj + 64] = lo32(a11) + hi32(a11);
        __syncthreads();

        // -------- Phase C: combine + log + blend + next p --------
        float tot = part[0][g][j] + part[1][g][j] +
                    part[2][g][j] + part[3][g][j];
        float sn = cp + __logf(tot) + em_r;
        s = mk_r * sn + (1.0f - mk_r) * s;
        if (j == 0) csh[t & 1][g] = s;
        float cn = csh[(t - 1) & 1][g];   // = s_{t-1}[0], written last step
        psh[g][j] = __expf(s - cn);
        cp = cn;
        if (t + 1 < LL) {
            em_r = emg[(size_t)(t + 1) * NN + j];
            mk_r = mkg[t + 1];
        }
        __syncthreads();
    }

    // ---- final logsumexp over states ----
    sred[g][j] = s;
    __syncthreads();
    const int w = tid >> 5, lane = tid & 31;
    if (w < GG) {
        float a = sred[w][lane];
        float b = sred[w][lane + 32];
        float c = sred[w][lane + 64];
        float d = sred[w][lane + 96];
        float mx = fmaxf(fmaxf(a, b), fmaxf(c, d));
#pragma unroll
        for (int o = 16; o; o >>= 1)
            mx = fmaxf(mx, __shfl_xor_sync(0xffffffffu, mx, o));
        float sum = __expf(a - mx) + __expf(b - mx) +
                    __expf(c - mx) + __expf(d - mx);
#pragma unroll
        for (int o = 16; o; o >>= 1)
            sum += __shfl_xor_sync(0xffffffffu, sum, o);
        if (lane == 0) g_norm[b0 + w] = mx + __logf(sum);
    }
}

// ---------------------------------------------------------------------------
// Kernel 2: path score. One block (128 threads) per batch.
// ---------------------------------------------------------------------------
__global__ __launch_bounds__(128)
void crf_path(const float* __restrict__ em,
              const int*   __restrict__ tgt,
              const float* __restrict__ mask,
              const float* __restrict__ start,
              const float* __restrict__ trans) {
    const int b = blockIdx.x;
    const int tid = threadIdx.x;
    __shared__ float red[128];

    const size_t embase = (size_t)b * LL * NN;
    float s = 0.0f;
    for (int t = tid; t < LL; t += 128) {
        if (t == 0) {
            int t0 = tgt[b * LL];
            s += start[t0] + em[embase + t0];
        } else {
            int prev = tgt[b * LL + t - 1];
            int cur  = tgt[b * LL + t];
            s += mask[b * LL + t] *
                 (trans[prev * NN + cur] + em[embase + (size_t)t * NN + cur]);
        }
    }
    red[tid] = s;
    __syncthreads();
#pragma unroll
    for (int o = 64; o; o >>= 1) {
        if (tid < o) red[tid] += red[tid + o];
        __syncthreads();
    }
    if (tid == 0) g_path[b] = red[0];
}

// ---------------------------------------------------------------------------
// Kernel 3: mean(normalizer - path)
// ---------------------------------------------------------------------------
__global__ __launch_bounds__(512)
void crf_final(float* __restrict__ out) {
    const int tid = threadIdx.x;
    __shared__ float wsum[16];
    float v = g_norm[tid] - g_path[tid];
#pragma unroll
    for (int o = 16; o; o >>= 1) v += __shfl_xor_sync(0xffffffffu, v, o);
    if ((tid & 31) == 0) wsum[tid >> 5] = v;
    __syncthreads();
    if (tid < 32) {
        float x = (tid < 16) ? wsum[tid] : 0.0f;
#pragma unroll
        for (int o = 8; o; o >>= 1) x += __shfl_xor_sync(0xffffffffu, x, o);
        if (tid == 0) out[0] = x * (1.0f / (float)BB);
    }
}

// ---------------------------------------------------------------------------
// Launch
// ---------------------------------------------------------------------------
extern "C" void kernel_launch(void* const* d_in, const int* in_sizes, int n_in,
                              void* d_out, int out_size) {
    const float* emission    = (const float*)d_in[0];
    const int*   target      = (const int*)  d_in[1];
    const float* mask        = (const float*)d_in[2];
    const float* start_trans = (const float*)d_in[3];
    const float* trans       = (const float*)d_in[4];
    float* out = (float*)d_out;

    crf_expE<<<64, 128>>>(trans);
    crf_forward<<<BB / GG, 256>>>(emission, mask, start_trans);
    crf_path<<<BB, 128>>>(emission, target, mask, start_trans, trans);
    crf_final<<<1, 512>>>(out);
}